// round 11
// baseline (speedup 1.0000x reference)
#include <cuda_runtime.h>
#include <cstdint>

// Problem shape (fixed by dataset): N=50000 nodes, E=800000, K=8, D=64.
#define DDIM 64
#define MAX_NODES 50000
#define MAX_RELS 8
#define MAX_EDGES 800000
#define SCAN_CHUNK 1024
#define MAX_CHUNKS ((MAX_NODES + SCAN_CHUNK - 1) / SCAN_CHUNK)

// Scratch: hw[n][k][o] (102.4 MB), tf32 W9, CSR arrays, packed edge records.
__device__ float g_hw[(size_t)MAX_NODES * MAX_RELS * DDIM];
__device__ float g_w9[9 * DDIM * DDIM];
__device__ int g_deg[MAX_NODES];
__device__ int g_rowptr[MAX_NODES + 1];
__device__ int g_cursor[MAX_NODES];
__device__ int g_blocksum[MAX_CHUNKS];
__device__ int2 g_epack[MAX_EDGES];   // {src*8+rel, bits(norm)} in CSR order

__device__ __forceinline__ uint32_t rna_tf32(float v) {
    uint32_t u;
    asm("cvt.rna.tf32.f32 %0, %1;" : "=r"(u) : "f"(v));
    return u;
}

// m16n8k8 tf32 mma, fp32 accumulate.
__device__ __forceinline__ void mma_tf32(float* c,
    uint32_t a0, uint32_t a1, uint32_t a2, uint32_t a3,
    uint32_t b0, uint32_t b1)
{
    asm volatile(
        "mma.sync.aligned.m16n8k8.row.col.f32.tf32.tf32.f32 "
        "{%0,%1,%2,%3}, {%4,%5,%6,%7}, {%8,%9}, {%0,%1,%2,%3};"
        : "+f"(c[0]), "+f"(c[1]), "+f"(c[2]), "+f"(c[3])
        : "r"(a0), "r"(a1), "r"(a2), "r"(a3), "r"(b0), "r"(b1));
}

// ---------------------------------------------------------------------------
// prep: W ++ loop_weight -> tf32-rna in g_w9; zero g_deg and g_blocksum.
// ---------------------------------------------------------------------------
__global__ void prep_kernel(const float* __restrict__ W,
                            const float* __restrict__ lw,
                            int n_nodes, int nchunks)
{
    int i = blockIdx.x * blockDim.x + threadIdx.x;
    if (i < 9 * DDIM * DDIM) {
        float v = (i < MAX_RELS * DDIM * DDIM) ? W[i] : lw[i - MAX_RELS * DDIM * DDIM];
        g_w9[i] = __uint_as_float(rna_tf32(v));
    }
    if (i < n_nodes) g_deg[i] = 0;
    if (i < nchunks) g_blocksum[i] = 0;
}

// hist: per-node degree atomics + per-chunk counts via smem histogram.
__global__ __launch_bounds__(256) void hist_kernel(const int* __restrict__ dst,
                                                   int n_edges, int nchunks)
{
    __shared__ int sm_chunk[MAX_CHUNKS];
    int t = threadIdx.x;
    if (t < nchunks) sm_chunk[t] = 0;
    __syncthreads();

    int e = blockIdx.x * 256 + t;
    if (e < n_edges) {
        int d = dst[e];
        atomicAdd(&g_deg[d], 1);
        atomicAdd(&sm_chunk[d >> 10], 1);
    }
    __syncthreads();
    if (t < nchunks) {
        int c = sm_chunk[t];
        if (c) atomicAdd(&g_blocksum[t], c);
    }
}

// chunk_scan: shfl-based block scan of degrees + self-computed chunk offset.
__global__ __launch_bounds__(SCAN_CHUNK) void chunk_scan_kernel(int n_nodes)
{
    __shared__ int warp_sums[32];
    __shared__ int warp_off[32];
    __shared__ int chunk_off_s;

    int t = threadIdx.x;
    int wid = t >> 5, lane = t & 31;
    int i = blockIdx.x * SCAN_CHUNK + t;
    int v = (i < n_nodes) ? g_deg[i] : 0;

    int s = v;
#pragma unroll
    for (int off = 1; off < 32; off <<= 1) {
        int u = __shfl_up_sync(0xFFFFFFFFu, s, off);
        if (lane >= off) s += u;
    }
    if (lane == 31) warp_sums[wid] = s;
    __syncthreads();

    if (wid == 0) {
        int acc = 0;
        for (int j = lane; j < blockIdx.x; j += 32) acc += g_blocksum[j];
#pragma unroll
        for (int off = 16; off > 0; off >>= 1)
            acc += __shfl_xor_sync(0xFFFFFFFFu, acc, off);
        if (lane == 0) chunk_off_s = acc;

        int ws = warp_sums[lane];
        int wss = ws;
#pragma unroll
        for (int off = 1; off < 32; off <<= 1) {
            int u = __shfl_up_sync(0xFFFFFFFFu, wss, off);
            if (lane >= off) wss += u;
        }
        warp_off[lane] = wss - ws;
    }
    __syncthreads();

    if (i < n_nodes) {
        int excl = chunk_off_s + warp_off[wid] + s - v;
        g_rowptr[i] = excl;
        g_cursor[i] = excl;
        if (i == n_nodes - 1) g_rowptr[n_nodes] = excl + v;
    }
}

// Scatter into CSR order: 4 edges/thread (chunk-strided, coalesced loads),
// 4 independent atomics in flight. NOTE: t must be < stride — threads past
// stride would re-scatter edges of chunk 1 (the R9 bug).
__global__ __launch_bounds__(256) void scatter_build_kernel(
    const int* __restrict__ src, const int* __restrict__ dst,
    const int* __restrict__ rel, const float* __restrict__ norm,
    int n_edges, int stride)
{
    int t = blockIdx.x * 256 + threadIdx.x;
    if (t >= stride) return;   // critical: each edge owned by exactly one thread

    int e0 = t;
    int e1 = t + stride;
    int e2 = t + 2 * stride;
    int e3 = t + 3 * stride;

    int d0 = (e0 < n_edges) ? dst[e0] : 0;
    int d1 = (e1 < n_edges) ? dst[e1] : 0;
    int d2 = (e2 < n_edges) ? dst[e2] : 0;
    int d3 = (e3 < n_edges) ? dst[e3] : 0;

    int p0 = (e0 < n_edges) ? atomicAdd(&g_cursor[d0], 1) : 0;
    int p1 = (e1 < n_edges) ? atomicAdd(&g_cursor[d1], 1) : 0;
    int p2 = (e2 < n_edges) ? atomicAdd(&g_cursor[d2], 1) : 0;
    int p3 = (e3 < n_edges) ? atomicAdd(&g_cursor[d3], 1) : 0;

    if (e0 < n_edges) g_epack[p0] = make_int2(src[e0] * MAX_RELS + rel[e0], __float_as_int(norm[e0]));
    if (e1 < n_edges) g_epack[p1] = make_int2(src[e1] * MAX_RELS + rel[e1], __float_as_int(norm[e1]));
    if (e2 < n_edges) g_epack[p2] = make_int2(src[e2] * MAX_RELS + rel[e2], __float_as_int(norm[e2]));
    if (e3 < n_edges) g_epack[p3] = make_int2(src[e3] * MAX_RELS + rel[e3], __float_as_int(norm[e3]));
}

// ---------------------------------------------------------------------------
// Fused tensor-core GEMM (unchanged from the 143us kernel). Static smem.
// ---------------------------------------------------------------------------
#define A2_STRIDE 36

__global__ __launch_bounds__(256) void rgcn_gemm9_kernel(
    const float* __restrict__ h, const float* __restrict__ bias,
    float* __restrict__ out, int n_nodes)
{
    __shared__ uint2 A2[64 * A2_STRIDE];
    __shared__ uint2 B2[64 * A2_STRIDE];

    const int tid = threadIdx.x;
    const int gr0 = blockIdx.x * 64;

    {
        int row = tid >> 2;
        int q = tid & 3;
        int gr = gr0 + row;
        uint2* Arow = A2 + row * A2_STRIDE;
        if (gr < n_nodes) {
            const float4* hp = (const float4*)(h + (size_t)gr * DDIM);
#pragma unroll
            for (int kk = 0; kk < 2; ++kk) {
                int ks = 2 * q + kk;
                float4 v0 = hp[2 * ks];
                float4 v1 = hp[2 * ks + 1];
                Arow[4 * ks + 0] = make_uint2(rna_tf32(v0.x), rna_tf32(v1.x));
                Arow[4 * ks + 1] = make_uint2(rna_tf32(v0.y), rna_tf32(v1.y));
                Arow[4 * ks + 2] = make_uint2(rna_tf32(v0.z), rna_tf32(v1.z));
                Arow[4 * ks + 3] = make_uint2(rna_tf32(v0.w), rna_tf32(v1.w));
            }
        } else {
#pragma unroll
            for (int kk = 0; kk < 2; ++kk) {
                int ks = 2 * q + kk;
                Arow[4 * ks + 0] = make_uint2(0u, 0u);
                Arow[4 * ks + 1] = make_uint2(0u, 0u);
                Arow[4 * ks + 2] = make_uint2(0u, 0u);
                Arow[4 * ks + 3] = make_uint2(0u, 0u);
            }
        }
    }

    const int wid = tid >> 5;
    const int lane = tid & 31;
    const int g = lane >> 2;
    const int t = lane & 3;
    const int m0 = (wid & 3) * 16;
    const int nbase = (wid >> 2) * 32;

    const uint2* ar0 = A2 + (m0 + g) * A2_STRIDE + t;
    const uint2* ar1 = A2 + (m0 + g + 8) * A2_STRIDE + t;
    const uint2* brb = B2 + (nbase + g) * A2_STRIDE + t;

    const int row_lo = gr0 + m0 + g;
    const int row_hi = row_lo + 8;

    for (int rel = 0; rel < 9; ++rel) {
        __syncthreads();
        {
            const float* Wk = g_w9 + rel * DDIM * DDIM;
#pragma unroll
            for (int i = 0; i < 8; ++i) {
                int e = tid + i * 256;
                int n = e & 63;
                int p = e >> 6;
                int ks = p >> 2, tt = p & 3;
                uint32_t b0 = __float_as_uint(Wk[(8 * ks + tt) * DDIM + n]);
                uint32_t b1 = __float_as_uint(Wk[(8 * ks + tt + 4) * DDIM + n]);
                B2[n * A2_STRIDE + p] = make_uint2(b0, b1);
            }
        }
        __syncthreads();

        float acc[4][4];
#pragma unroll
        for (int j = 0; j < 4; ++j)
#pragma unroll
            for (int qq = 0; qq < 4; ++qq) acc[j][qq] = 0.f;

#pragma unroll
        for (int ks = 0; ks < 8; ++ks) {
            uint2 A0 = ar0[4 * ks];
            uint2 A1 = ar1[4 * ks];
#pragma unroll
            for (int j = 0; j < 4; ++j) {
                uint2 B = brb[j * 8 * A2_STRIDE + 4 * ks];
                mma_tf32(acc[j], A0.x, A1.x, A0.y, A1.y, B.x, B.y);
            }
        }

        if (rel < 8) {
#pragma unroll
            for (int j = 0; j < 4; ++j) {
                int col = nbase + 8 * j + 2 * t;
                if (row_lo < n_nodes)
                    *(float2*)&g_hw[((size_t)row_lo * MAX_RELS + rel) * DDIM + col] =
                        make_float2(acc[j][0], acc[j][1]);
                if (row_hi < n_nodes)
                    *(float2*)&g_hw[((size_t)row_hi * MAX_RELS + rel) * DDIM + col] =
                        make_float2(acc[j][2], acc[j][3]);
            }
        } else {
#pragma unroll
            for (int j = 0; j < 4; ++j) {
                int col = nbase + 8 * j + 2 * t;
                float b0 = bias[col], b1 = bias[col + 1];
                if (row_lo < n_nodes)
                    *(float2*)&out[(size_t)row_lo * DDIM + col] =
                        make_float2(acc[j][0] + b0, acc[j][1] + b1);
                if (row_hi < n_nodes)
                    *(float2*)&out[(size_t)row_hi * DDIM + col] =
                        make_float2(acc[j][2] + b0, acc[j][3] + b1);
            }
        }
    }
}

// ---------------------------------------------------------------------------
// Aggregation: ONE NODE PER BLOCK (128 threads = 4 warps). Warps split the
// edge segment (warp w takes edges beg+w, beg+w+4, ...), each covering all 64
// columns (lane = float2). Partials combined in smem; warp 0 adds the loop
// term and applies ReLU. Per-warp trips ~ deg/4 -> 4x shorter degree tail.
// ---------------------------------------------------------------------------
__global__ __launch_bounds__(128) void agg_kernel(float* __restrict__ out, int n_nodes)
{
    __shared__ float2 sm[4][32];

    int node = blockIdx.x;
    int wid = threadIdx.x >> 5;
    int lane = threadIdx.x & 31;

    int beg = g_rowptr[node];
    int end = g_rowptr[node + 1];

    float ax = 0.f, ay = 0.f;
    int i = beg + wid;
    // pairs (i, i+4), stride 8, per-warp stride 4
    for (; i + 4 < end; i += 8) {
        int2 p0 = g_epack[i];
        int2 p1 = g_epack[i + 4];
        float2 v0 = ((const float2*)(g_hw + (size_t)p0.x * DDIM))[lane];
        float2 v1 = ((const float2*)(g_hw + (size_t)p1.x * DDIM))[lane];
        float n0 = __int_as_float(p0.y);
        float n1 = __int_as_float(p1.y);
        ax += v0.x * n0; ay += v0.y * n0;
        ax += v1.x * n1; ay += v1.y * n1;
    }
    if (i < end) {
        int2 p = g_epack[i];
        float2 v = ((const float2*)(g_hw + (size_t)p.x * DDIM))[lane];
        float nn = __int_as_float(p.y);
        ax += v.x * nn; ay += v.y * nn;
    }

    sm[wid][lane] = make_float2(ax, ay);
    __syncthreads();

    if (wid == 0) {
        float2 a0 = sm[0][lane];
        float2 a1 = sm[1][lane];
        float2 a2 = sm[2][lane];
        float2 a3 = sm[3][lane];
        float sx = a0.x + a1.x + a2.x + a3.x;
        float sy = a0.y + a1.y + a2.y + a3.y;
        float2* o = (float2*)(out + (size_t)node * DDIM);
        float2 base = o[lane];
        o[lane] = make_float2(fmaxf(base.x + sx, 0.0f), fmaxf(base.y + sy, 0.0f));
    }
}

// ---------------------------------------------------------------------------
// Inputs (metadata order): h, norm, W, loop_weight, h_bias, src, dst, r
// ---------------------------------------------------------------------------
extern "C" void kernel_launch(void* const* d_in, const int* in_sizes, int n_in,
                              void* d_out, int out_size)
{
    const float* h    = (const float*)d_in[0];
    const float* norm = (const float*)d_in[1];
    const float* W    = (const float*)d_in[2];
    const float* lw   = (const float*)d_in[3];
    const float* bias = (const float*)d_in[4];
    const int*   src  = (const int*)d_in[5];
    const int*   dst  = (const int*)d_in[6];
    const int*   rel  = (const int*)d_in[7];
    float* out = (float*)d_out;

    int n_nodes = in_sizes[0] / DDIM;
    int n_edges = in_sizes[5];

    int nb_edges = (n_edges + 255) / 256;
    int nchunks = (n_nodes + SCAN_CHUNK - 1) / SCAN_CHUNK;

    // prep weights + zero counters
    int prep_n = (9 * DDIM * DDIM > n_nodes) ? 9 * DDIM * DDIM : n_nodes;
    prep_kernel<<<(prep_n + 255) / 256, 256>>>(W, lw, n_nodes, nchunks);

    // CSR build
    hist_kernel<<<nb_edges, 256>>>(dst, n_edges, nchunks);
    chunk_scan_kernel<<<nchunks, SCAN_CHUNK>>>(n_nodes);
    int sc_stride = (n_edges + 3) / 4;
    scatter_build_kernel<<<(sc_stride + 255) / 256, 256>>>(src, dst, rel, norm,
                                                           n_edges, sc_stride);

    // Fused tensor-core GEMM: g_hw (rels 0..7) + d_out = h@loop + bias
    int ntiles = (n_nodes + 63) / 64;
    rgcn_gemm9_kernel<<<ntiles, 256>>>(h, bias, out, n_nodes);

    // Per-node aggregation: one block (4 warps) per node, edges split by warp
    agg_kernel<<<n_nodes, 128>>>(out, n_nodes);
}

// round 12
// speedup vs baseline: 1.2673x; 1.2673x over previous
#include <cuda_runtime.h>
#include <cstdint>

// Problem shape (fixed by dataset): N=50000 nodes, E=800000, K=8, D=64.
#define DDIM 64
#define MAX_NODES 50000
#define MAX_RELS 8
#define MAX_EDGES 800000
#define SCAN_CHUNK 1024
#define MAX_CHUNKS ((MAX_NODES + SCAN_CHUNK - 1) / SCAN_CHUNK)

// Scratch: hw[n][k][o] (102.4 MB), CSR arrays, packed edge records.
// g_deg / g_blocksum are zero-initialized at module load and re-zeroed by
// rgcn_gemm9_kernel (which runs after chunk_scan consumed them) for the next
// graph replay.
__device__ float g_hw[(size_t)MAX_NODES * MAX_RELS * DDIM];
__device__ int g_deg[MAX_NODES];
__device__ int g_rowptr[MAX_NODES + 1];
__device__ int g_cursor[MAX_NODES];
__device__ int g_blocksum[MAX_CHUNKS];
__device__ int2 g_epack[MAX_EDGES];   // {src*8+rel, bits(norm)} in CSR order

__device__ __forceinline__ uint32_t rna_tf32(float v) {
    uint32_t u;
    asm("cvt.rna.tf32.f32 %0, %1;" : "=r"(u) : "f"(v));
    return u;
}

// m16n8k8 tf32 mma, fp32 accumulate.
__device__ __forceinline__ void mma_tf32(float* c,
    uint32_t a0, uint32_t a1, uint32_t a2, uint32_t a3,
    uint32_t b0, uint32_t b1)
{
    asm volatile(
        "mma.sync.aligned.m16n8k8.row.col.f32.tf32.tf32.f32 "
        "{%0,%1,%2,%3}, {%4,%5,%6,%7}, {%8,%9}, {%0,%1,%2,%3};"
        : "+f"(c[0]), "+f"(c[1]), "+f"(c[2]), "+f"(c[3])
        : "r"(a0), "r"(a1), "r"(a2), "r"(a3), "r"(b0), "r"(b1));
}

// hist: per-node degree atomics + per-chunk counts via smem histogram.
__global__ __launch_bounds__(256) void hist_kernel(const int* __restrict__ dst,
                                                   int n_edges, int nchunks)
{
    __shared__ int sm_chunk[MAX_CHUNKS];
    int t = threadIdx.x;
    if (t < nchunks) sm_chunk[t] = 0;
    __syncthreads();

    int e = blockIdx.x * 256 + t;
    if (e < n_edges) {
        int d = dst[e];
        atomicAdd(&g_deg[d], 1);
        atomicAdd(&sm_chunk[d >> 10], 1);
    }
    __syncthreads();
    if (t < nchunks) {
        int c = sm_chunk[t];
        if (c) atomicAdd(&g_blocksum[t], c);
    }
}

// chunk_scan: shfl-based block scan of degrees + self-computed chunk offset.
__global__ __launch_bounds__(SCAN_CHUNK) void chunk_scan_kernel(int n_nodes)
{
    __shared__ int warp_sums[32];
    __shared__ int warp_off[32];
    __shared__ int chunk_off_s;

    int t = threadIdx.x;
    int wid = t >> 5, lane = t & 31;
    int i = blockIdx.x * SCAN_CHUNK + t;
    int v = (i < n_nodes) ? g_deg[i] : 0;

    int s = v;
#pragma unroll
    for (int off = 1; off < 32; off <<= 1) {
        int u = __shfl_up_sync(0xFFFFFFFFu, s, off);
        if (lane >= off) s += u;
    }
    if (lane == 31) warp_sums[wid] = s;
    __syncthreads();

    if (wid == 0) {
        int acc = 0;
        for (int j = lane; j < blockIdx.x; j += 32) acc += g_blocksum[j];
#pragma unroll
        for (int off = 16; off > 0; off >>= 1)
            acc += __shfl_xor_sync(0xFFFFFFFFu, acc, off);
        if (lane == 0) chunk_off_s = acc;

        int ws = warp_sums[lane];
        int wss = ws;
#pragma unroll
        for (int off = 1; off < 32; off <<= 1) {
            int u = __shfl_up_sync(0xFFFFFFFFu, wss, off);
            if (lane >= off) wss += u;
        }
        warp_off[lane] = wss - ws;
    }
    __syncthreads();

    if (i < n_nodes) {
        int excl = chunk_off_s + warp_off[wid] + s - v;
        g_rowptr[i] = excl;
        g_cursor[i] = excl;
        if (i == n_nodes - 1) g_rowptr[n_nodes] = excl + v;
    }
}

// Scatter into CSR order: 1 edge/thread (the measured-best R7/R8 form).
__global__ __launch_bounds__(256) void scatter_build_kernel(
    const int* __restrict__ src, const int* __restrict__ dst,
    const int* __restrict__ rel, const float* __restrict__ norm,
    int n_edges)
{
    int e = blockIdx.x * 256 + threadIdx.x;
    if (e >= n_edges) return;
    int pos = atomicAdd(&g_cursor[dst[e]], 1);
    g_epack[pos] = make_int2(src[e] * MAX_RELS + rel[e], __float_as_int(norm[e]));
}

// ---------------------------------------------------------------------------
// Fused tensor-core GEMM. Static smem. W/lw converted to tf32 on the fly in
// the B-tile fill (prep kernel eliminated). Also re-zeros g_deg / g_blocksum
// for the next graph replay (safe: runs after chunk_scan consumed them).
// ---------------------------------------------------------------------------
#define A2_STRIDE 36

__global__ __launch_bounds__(256) void rgcn_gemm9_kernel(
    const float* __restrict__ h, const float* __restrict__ W,
    const float* __restrict__ lw, const float* __restrict__ bias,
    float* __restrict__ out, int n_nodes, int nchunks)
{
    __shared__ uint2 A2[64 * A2_STRIDE];
    __shared__ uint2 B2[64 * A2_STRIDE];

    const int tid = threadIdx.x;
    const int gr0 = blockIdx.x * 64;

    // Re-zero CSR counters for the next replay (consumed earlier this replay).
    {
        int gi = blockIdx.x * 256 + tid;
        if (gi < n_nodes) g_deg[gi] = 0;
        if (gi < nchunks) g_blocksum[gi] = 0;
    }

    // ---- Fill A tile: thread -> (row = tid>>2, quarter q = tid&3). ----
    {
        int row = tid >> 2;
        int q = tid & 3;
        int gr = gr0 + row;
        uint2* Arow = A2 + row * A2_STRIDE;
        if (gr < n_nodes) {
            const float4* hp = (const float4*)(h + (size_t)gr * DDIM);
#pragma unroll
            for (int kk = 0; kk < 2; ++kk) {
                int ks = 2 * q + kk;
                float4 v0 = hp[2 * ks];
                float4 v1 = hp[2 * ks + 1];
                Arow[4 * ks + 0] = make_uint2(rna_tf32(v0.x), rna_tf32(v1.x));
                Arow[4 * ks + 1] = make_uint2(rna_tf32(v0.y), rna_tf32(v1.y));
                Arow[4 * ks + 2] = make_uint2(rna_tf32(v0.z), rna_tf32(v1.z));
                Arow[4 * ks + 3] = make_uint2(rna_tf32(v0.w), rna_tf32(v1.w));
            }
        } else {
#pragma unroll
            for (int kk = 0; kk < 2; ++kk) {
                int ks = 2 * q + kk;
                Arow[4 * ks + 0] = make_uint2(0u, 0u);
                Arow[4 * ks + 1] = make_uint2(0u, 0u);
                Arow[4 * ks + 2] = make_uint2(0u, 0u);
                Arow[4 * ks + 3] = make_uint2(0u, 0u);
            }
        }
    }

    const int wid = tid >> 5;
    const int lane = tid & 31;
    const int g = lane >> 2;
    const int t = lane & 3;
    const int m0 = (wid & 3) * 16;
    const int nbase = (wid >> 2) * 32;

    const uint2* ar0 = A2 + (m0 + g) * A2_STRIDE + t;
    const uint2* ar1 = A2 + (m0 + g + 8) * A2_STRIDE + t;
    const uint2* brb = B2 + (nbase + g) * A2_STRIDE + t;

    const int row_lo = gr0 + m0 + g;
    const int row_hi = row_lo + 8;

    for (int rel = 0; rel < 9; ++rel) {
        __syncthreads();
        {
            const float* Wk = (rel < 8) ? (W + rel * DDIM * DDIM) : lw;
#pragma unroll
            for (int i = 0; i < 8; ++i) {
                int e = tid + i * 256;
                int n = e & 63;
                int p = e >> 6;
                int ks = p >> 2, tt = p & 3;
                uint32_t b0 = rna_tf32(Wk[(8 * ks + tt) * DDIM + n]);
                uint32_t b1 = rna_tf32(Wk[(8 * ks + tt + 4) * DDIM + n]);
                B2[n * A2_STRIDE + p] = make_uint2(b0, b1);
            }
        }
        __syncthreads();

        float acc[4][4];
#pragma unroll
        for (int j = 0; j < 4; ++j)
#pragma unroll
            for (int qq = 0; qq < 4; ++qq) acc[j][qq] = 0.f;

#pragma unroll
        for (int ks = 0; ks < 8; ++ks) {
            uint2 A0 = ar0[4 * ks];
            uint2 A1 = ar1[4 * ks];
#pragma unroll
            for (int j = 0; j < 4; ++j) {
                uint2 B = brb[j * 8 * A2_STRIDE + 4 * ks];
                mma_tf32(acc[j], A0.x, A1.x, A0.y, A1.y, B.x, B.y);
            }
        }

        if (rel < 8) {
#pragma unroll
            for (int j = 0; j < 4; ++j) {
                int col = nbase + 8 * j + 2 * t;
                if (row_lo < n_nodes)
                    *(float2*)&g_hw[((size_t)row_lo * MAX_RELS + rel) * DDIM + col] =
                        make_float2(acc[j][0], acc[j][1]);
                if (row_hi < n_nodes)
                    *(float2*)&g_hw[((size_t)row_hi * MAX_RELS + rel) * DDIM + col] =
                        make_float2(acc[j][2], acc[j][3]);
            }
        } else {
#pragma unroll
            for (int j = 0; j < 4; ++j) {
                int col = nbase + 8 * j + 2 * t;
                float b0 = bias[col], b1 = bias[col + 1];
                if (row_lo < n_nodes)
                    *(float2*)&out[(size_t)row_lo * DDIM + col] =
                        make_float2(acc[j][0] + b0, acc[j][1] + b1);
                if (row_hi < n_nodes)
                    *(float2*)&out[(size_t)row_hi * DDIM + col] =
                        make_float2(acc[j][2] + b0, acc[j][3] + b1);
            }
        }
    }
}

// ---------------------------------------------------------------------------
// Aggregation (R7 form, measured-best): ONE WARP per dst node, lane = float2
// (256B coalesced gather per edge). 8-way unrolled for MLP 8. Fused loop-term
// + ReLU.
// ---------------------------------------------------------------------------
__global__ __launch_bounds__(256) void agg_kernel(float* __restrict__ out, int n_nodes)
{
    int warp = (blockIdx.x * 256 + threadIdx.x) >> 5;
    int lane = threadIdx.x & 31;
    if (warp >= n_nodes) return;

    int beg = g_rowptr[warp];
    int end = g_rowptr[warp + 1];

    float ax = 0.f, ay = 0.f;
    int i = beg;
    for (; i + 7 < end; i += 8) {
        int2 p0 = g_epack[i + 0];
        int2 p1 = g_epack[i + 1];
        int2 p2 = g_epack[i + 2];
        int2 p3 = g_epack[i + 3];
        int2 p4 = g_epack[i + 4];
        int2 p5 = g_epack[i + 5];
        int2 p6 = g_epack[i + 6];
        int2 p7 = g_epack[i + 7];
        float2 v0 = ((const float2*)(g_hw + (size_t)p0.x * DDIM))[lane];
        float2 v1 = ((const float2*)(g_hw + (size_t)p1.x * DDIM))[lane];
        float2 v2 = ((const float2*)(g_hw + (size_t)p2.x * DDIM))[lane];
        float2 v3 = ((const float2*)(g_hw + (size_t)p3.x * DDIM))[lane];
        float2 v4 = ((const float2*)(g_hw + (size_t)p4.x * DDIM))[lane];
        float2 v5 = ((const float2*)(g_hw + (size_t)p5.x * DDIM))[lane];
        float2 v6 = ((const float2*)(g_hw + (size_t)p6.x * DDIM))[lane];
        float2 v7 = ((const float2*)(g_hw + (size_t)p7.x * DDIM))[lane];
        ax += v0.x * __int_as_float(p0.y); ay += v0.y * __int_as_float(p0.y);
        ax += v1.x * __int_as_float(p1.y); ay += v1.y * __int_as_float(p1.y);
        ax += v2.x * __int_as_float(p2.y); ay += v2.y * __int_as_float(p2.y);
        ax += v3.x * __int_as_float(p3.y); ay += v3.y * __int_as_float(p3.y);
        ax += v4.x * __int_as_float(p4.y); ay += v4.y * __int_as_float(p4.y);
        ax += v5.x * __int_as_float(p5.y); ay += v5.y * __int_as_float(p5.y);
        ax += v6.x * __int_as_float(p6.y); ay += v6.y * __int_as_float(p6.y);
        ax += v7.x * __int_as_float(p7.y); ay += v7.y * __int_as_float(p7.y);
    }
    for (; i < end; ++i) {
        int2 p = g_epack[i];
        float2 v = ((const float2*)(g_hw + (size_t)p.x * DDIM))[lane];
        float nn = __int_as_float(p.y);
        ax += v.x * nn; ay += v.y * nn;
    }

    float2* o = (float2*)(out + (size_t)warp * DDIM);
    float2 base = o[lane];
    o[lane] = make_float2(fmaxf(base.x + ax, 0.0f), fmaxf(base.y + ay, 0.0f));
}

// ---------------------------------------------------------------------------
// Inputs (metadata order): h, norm, W, loop_weight, h_bias, src, dst, r
// 5 launches: hist, chunk_scan, scatter, gemm, agg.
// ---------------------------------------------------------------------------
extern "C" void kernel_launch(void* const* d_in, const int* in_sizes, int n_in,
                              void* d_out, int out_size)
{
    const float* h    = (const float*)d_in[0];
    const float* norm = (const float*)d_in[1];
    const float* W    = (const float*)d_in[2];
    const float* lw   = (const float*)d_in[3];
    const float* bias = (const float*)d_in[4];
    const int*   src  = (const int*)d_in[5];
    const int*   dst  = (const int*)d_in[6];
    const int*   rel  = (const int*)d_in[7];
    float* out = (float*)d_out;

    int n_nodes = in_sizes[0] / DDIM;
    int n_edges = in_sizes[5];

    int nb_edges = (n_edges + 255) / 256;
    int nchunks = (n_nodes + SCAN_CHUNK - 1) / SCAN_CHUNK;

    // CSR build (g_deg/g_blocksum pre-zeroed by previous replay's gemm,
    // or by static zero-init on the very first call)
    hist_kernel<<<nb_edges, 256>>>(dst, n_edges, nchunks);
    chunk_scan_kernel<<<nchunks, SCAN_CHUNK>>>(n_nodes);
    scatter_build_kernel<<<nb_edges, 256>>>(src, dst, rel, norm, n_edges);

    // Fused tensor-core GEMM (also re-zeros CSR counters for next replay)
    int ntiles = (n_nodes + 63) / 64;
    rgcn_gemm9_kernel<<<ntiles, 256>>>(h, W, lw, bias, out, n_nodes, nchunks);

    // Per-node aggregation: one warp per node, fused ReLU
    long long agg_threads = (long long)n_nodes * 32;
    agg_kernel<<<(int)((agg_threads + 255) / 256), 256>>>(out, n_nodes);
}

// round 14
// speedup vs baseline: 1.4059x; 1.1093x over previous
#include <cuda_runtime.h>
#include <cstdint>

// Problem shape (fixed by dataset): N=50000 nodes, E=800000, K=8, D=64.
#define DDIM 64
#define MAX_NODES 50000
#define MAX_RELS 8
#define MAX_EDGES 800000
#define SCAN_CHUNK 1024
#define MAX_CHUNKS ((MAX_NODES + SCAN_CHUNK - 1) / SCAN_CHUNK)

// Scratch: hw[n][k][o] (102.4 MB), CSR arrays, packed edge records.
// g_deg / g_blocksum zero at module load; re-zeroed by the GEMM kernel
// (which runs after chunk_scan consumed them) for the next graph replay.
__device__ float g_hw[(size_t)MAX_NODES * MAX_RELS * DDIM];
__device__ int g_deg[MAX_NODES];
__device__ int g_rowptr[MAX_NODES + 1];
__device__ int g_cursor[MAX_NODES];
__device__ int g_blocksum[MAX_CHUNKS];
__device__ int2 g_epack[MAX_EDGES];   // {src*8+rel, bits(norm)} in CSR order

__device__ __forceinline__ uint32_t rna_tf32(float v) {
    uint32_t u;
    asm("cvt.rna.tf32.f32 %0, %1;" : "=r"(u) : "f"(v));
    return u;
}

// m16n8k8 tf32 mma, fp32 accumulate.
__device__ __forceinline__ void mma_tf32(float* c,
    uint32_t a0, uint32_t a1, uint32_t a2, uint32_t a3,
    uint32_t b0, uint32_t b1)
{
    asm volatile(
        "mma.sync.aligned.m16n8k8.row.col.f32.tf32.tf32.f32 "
        "{%0,%1,%2,%3}, {%4,%5,%6,%7}, {%8,%9}, {%0,%1,%2,%3};"
        : "+f"(c[0]), "+f"(c[1]), "+f"(c[2]), "+f"(c[3])
        : "r"(a0), "r"(a1), "r"(a2), "r"(a3), "r"(b0), "r"(b1));
}

// hist: per-node degree atomics + per-chunk counts via smem histogram.
__global__ __launch_bounds__(256) void hist_kernel(const int* __restrict__ dst,
                                                   int n_edges, int nchunks)
{
    __shared__ int sm_chunk[MAX_CHUNKS];
    int t = threadIdx.x;
    if (t < nchunks) sm_chunk[t] = 0;
    __syncthreads();

    int e = blockIdx.x * 256 + t;
    if (e < n_edges) {
        int d = dst[e];
        atomicAdd(&g_deg[d], 1);
        atomicAdd(&sm_chunk[d >> 10], 1);
    }
    __syncthreads();
    if (t < nchunks) {
        int c = sm_chunk[t];
        if (c) atomicAdd(&g_blocksum[t], c);
    }
}

// chunk_scan: shfl-based block scan of degrees + self-computed chunk offset.
__global__ __launch_bounds__(SCAN_CHUNK) void chunk_scan_kernel(int n_nodes)
{
    __shared__ int warp_sums[32];
    __shared__ int warp_off[32];
    __shared__ int chunk_off_s;

    int t = threadIdx.x;
    int wid = t >> 5, lane = t & 31;
    int i = blockIdx.x * SCAN_CHUNK + t;
    int v = (i < n_nodes) ? g_deg[i] : 0;

    int s = v;
#pragma unroll
    for (int off = 1; off < 32; off <<= 1) {
        int u = __shfl_up_sync(0xFFFFFFFFu, s, off);
        if (lane >= off) s += u;
    }
    if (lane == 31) warp_sums[wid] = s;
    __syncthreads();

    if (wid == 0) {
        int acc = 0;
        for (int j = lane; j < blockIdx.x; j += 32) acc += g_blocksum[j];
#pragma unroll
        for (int off = 16; off > 0; off >>= 1)
            acc += __shfl_xor_sync(0xFFFFFFFFu, acc, off);
        if (lane == 0) chunk_off_s = acc;

        int ws = warp_sums[lane];
        int wss = ws;
#pragma unroll
        for (int off = 1; off < 32; off <<= 1) {
            int u = __shfl_up_sync(0xFFFFFFFFu, wss, off);
            if (lane >= off) wss += u;
        }
        warp_off[lane] = wss - ws;
    }
    __syncthreads();

    if (i < n_nodes) {
        int excl = chunk_off_s + warp_off[wid] + s - v;
        g_rowptr[i] = excl;
        g_cursor[i] = excl;
        if (i == n_nodes - 1) g_rowptr[n_nodes] = excl + v;
    }
}

// Scatter into CSR order: 1 edge/thread (measured-best form).
__global__ __launch_bounds__(256) void scatter_build_kernel(
    const int* __restrict__ src, const int* __restrict__ dst,
    const int* __restrict__ rel, const float* __restrict__ norm,
    int n_edges)
{
    int e = blockIdx.x * 256 + threadIdx.x;
    if (e >= n_edges) return;
    int pos = atomicAdd(&g_cursor[dst[e]], 1);
    g_epack[pos] = make_int2(src[e] * MAX_RELS + rel[e], __float_as_int(norm[e]));
}

// ---------------------------------------------------------------------------
// Fused tensor-core GEMM, v2: 128 threads / 4 warps, warp tile m32 x n32,
// A fragments hoisted to registers once and reused across all 9 rels.
// LDS per warp per rel: 32 (B only) feeding 8 mmas, vs 48 per m16n32 before.
// Static smem 37 KB unchanged. Also re-zeros g_deg / g_blocksum for replay.
// ---------------------------------------------------------------------------
#define A2_STRIDE 36

__global__ __launch_bounds__(128) void rgcn_gemm9_kernel(
    const float* __restrict__ h, const float* __restrict__ W,
    const float* __restrict__ lw, const float* __restrict__ bias,
    float* __restrict__ out, int n_nodes, int nchunks)
{
    __shared__ uint2 A2[64 * A2_STRIDE];
    __shared__ uint2 B2[64 * A2_STRIDE];

    const int tid = threadIdx.x;
    const int gr0 = blockIdx.x * 64;

    // Re-zero CSR counters for the next replay (782*128 = 100096 >= n_nodes).
    {
        int gi = blockIdx.x * 128 + tid;
        if (gi < n_nodes) g_deg[gi] = 0;
        if (gi < nchunks) g_blocksum[gi] = 0;
    }

    // ---- Fill A tile: thread -> (row = tid>>1, half q = tid&1), 16 uint2 each.
    {
        int row = tid >> 1;
        int q = tid & 1;               // handles ks = 4q .. 4q+3
        int gr = gr0 + row;
        uint2* Arow = A2 + row * A2_STRIDE;
        if (gr < n_nodes) {
            const float4* hp = (const float4*)(h + (size_t)gr * DDIM);
#pragma unroll
            for (int kk = 0; kk < 4; ++kk) {
                int ks = 4 * q + kk;
                float4 v0 = hp[2 * ks];
                float4 v1 = hp[2 * ks + 1];
                Arow[4 * ks + 0] = make_uint2(rna_tf32(v0.x), rna_tf32(v1.x));
                Arow[4 * ks + 1] = make_uint2(rna_tf32(v0.y), rna_tf32(v1.y));
                Arow[4 * ks + 2] = make_uint2(rna_tf32(v0.z), rna_tf32(v1.z));
                Arow[4 * ks + 3] = make_uint2(rna_tf32(v0.w), rna_tf32(v1.w));
            }
        } else {
#pragma unroll
            for (int kk = 0; kk < 4; ++kk) {
                int ks = 4 * q + kk;
                Arow[4 * ks + 0] = make_uint2(0u, 0u);
                Arow[4 * ks + 1] = make_uint2(0u, 0u);
                Arow[4 * ks + 2] = make_uint2(0u, 0u);
                Arow[4 * ks + 3] = make_uint2(0u, 0u);
            }
        }
    }
    __syncthreads();

    const int wid = tid >> 5;      // 0..3
    const int lane = tid & 31;
    const int g = lane >> 2;       // 0..7
    const int t = lane & 3;        // 0..3
    const int m0 = (wid & 1) * 32;
    const int nbase = (wid >> 1) * 32;

    // ---- Hoist A fragments to registers (reused for all 9 rels). ----
    uint2 afr[4][8];
#pragma unroll
    for (int ks = 0; ks < 8; ++ks) {
        afr[0][ks] = A2[(m0 + g) * A2_STRIDE + 4 * ks + t];
        afr[1][ks] = A2[(m0 + g + 8) * A2_STRIDE + 4 * ks + t];
        afr[2][ks] = A2[(m0 + 16 + g) * A2_STRIDE + 4 * ks + t];
        afr[3][ks] = A2[(m0 + 24 + g) * A2_STRIDE + 4 * ks + t];
    }

    const uint2* brb = B2 + (nbase + g) * A2_STRIDE + t;
    const int row0 = gr0 + m0 + g;
    const int row1 = row0 + 8;
    const int row2 = row0 + 16;
    const int row3 = row0 + 24;

    for (int rel = 0; rel < 9; ++rel) {
        __syncthreads();
        {
            const float* Wk = (rel < 8) ? (W + rel * DDIM * DDIM) : lw;
#pragma unroll
            for (int i = 0; i < 16; ++i) {
                int e = tid + i * 128;          // 2048 uint2
                int n = e & 63;
                int p = e >> 6;                 // 4*ks + tt
                int ks = p >> 2, tt = p & 3;
                uint32_t b0 = rna_tf32(Wk[(8 * ks + tt) * DDIM + n]);
                uint32_t b1 = rna_tf32(Wk[(8 * ks + tt + 4) * DDIM + n]);
                B2[n * A2_STRIDE + p] = make_uint2(b0, b1);
            }
        }
        __syncthreads();

        float acc0[4][4];
        float acc1[4][4];
#pragma unroll
        for (int j = 0; j < 4; ++j)
#pragma unroll
            for (int qq = 0; qq < 4; ++qq) { acc0[j][qq] = 0.f; acc1[j][qq] = 0.f; }

#pragma unroll
        for (int ks = 0; ks < 8; ++ks) {
            uint2 A00 = afr[0][ks];
            uint2 A01 = afr[1][ks];
            uint2 A10 = afr[2][ks];
            uint2 A11 = afr[3][ks];
#pragma unroll
            for (int j = 0; j < 4; ++j) {
                uint2 B = brb[j * 8 * A2_STRIDE + 4 * ks];
                mma_tf32(acc0[j], A00.x, A01.x, A00.y, A01.y, B.x, B.y);
                mma_tf32(acc1[j], A10.x, A11.x, A10.y, A11.y, B.x, B.y);
            }
        }

        if (rel < 8) {
#pragma unroll
            for (int j = 0; j < 4; ++j) {
                int col = nbase + 8 * j + 2 * t;
                if (row0 < n_nodes)
                    *(float2*)&g_hw[((size_t)row0 * MAX_RELS + rel) * DDIM + col] =
                        make_float2(acc0[j][0], acc0[j][1]);
                if (row1 < n_nodes)
                    *(float2*)&g_hw[((size_t)row1 * MAX_RELS + rel) * DDIM + col] =
                        make_float2(acc0[j][2], acc0[j][3]);
                if (row2 < n_nodes)
                    *(float2*)&g_hw[((size_t)row2 * MAX_RELS + rel) * DDIM + col] =
                        make_float2(acc1[j][0], acc1[j][1]);
                if (row3 < n_nodes)
                    *(float2*)&g_hw[((size_t)row3 * MAX_RELS + rel) * DDIM + col] =
                        make_float2(acc1[j][2], acc1[j][3]);
            }
        } else {
#pragma unroll
            for (int j = 0; j < 4; ++j) {
                int col = nbase + 8 * j + 2 * t;
                float b0 = bias[col], b1 = bias[col + 1];
                if (row0 < n_nodes)
                    *(float2*)&out[(size_t)row0 * DDIM + col] =
                        make_float2(acc0[j][0] + b0, acc0[j][1] + b1);
                if (row1 < n_nodes)
                    *(float2*)&out[(size_t)row1 * DDIM + col] =
                        make_float2(acc0[j][2] + b0, acc0[j][3] + b1);
                if (row2 < n_nodes)
                    *(float2*)&out[(size_t)row2 * DDIM + col] =
                        make_float2(acc1[j][0] + b0, acc1[j][1] + b1);
                if (row3 < n_nodes)
                    *(float2*)&out[(size_t)row3 * DDIM + col] =
                        make_float2(acc1[j][2] + b0, acc1[j][3] + b1);
            }
        }
    }
}

// ---------------------------------------------------------------------------
// Aggregation (measured-best): ONE WARP per dst node, lane = float2 (256B
// coalesced gather per edge), 8-way unrolled, fused loop-term + ReLU.
// ---------------------------------------------------------------------------
__global__ __launch_bounds__(256) void agg_kernel(float* __restrict__ out, int n_nodes)
{
    int warp = (blockIdx.x * 256 + threadIdx.x) >> 5;
    int lane = threadIdx.x & 31;
    if (warp >= n_nodes) return;

    int beg = g_rowptr[warp];
    int end = g_rowptr[warp + 1];

    float ax = 0.f, ay = 0.f;
    int i = beg;
    for (; i + 7 < end; i += 8) {
        int2 p0 = g_epack[i + 0];
        int2 p1 = g_epack[i + 1];
        int2 p2 = g_epack[i + 2];
        int2 p3 = g_epack[i + 3];
        int2 p4 = g_epack[i + 4];
        int2 p5 = g_epack[i + 5];
        int2 p6 = g_epack[i + 6];
        int2 p7 = g_epack[i + 7];
        float2 v0 = ((const float2*)(g_hw + (size_t)p0.x * DDIM))[lane];
        float2 v1 = ((const float2*)(g_hw + (size_t)p1.x * DDIM))[lane];
        float2 v2 = ((const float2*)(g_hw + (size_t)p2.x * DDIM))[lane];
        float2 v3 = ((const float2*)(g_hw + (size_t)p3.x * DDIM))[lane];
        float2 v4 = ((const float2*)(g_hw + (size_t)p4.x * DDIM))[lane];
        float2 v5 = ((const float2*)(g_hw + (size_t)p5.x * DDIM))[lane];
        float2 v6 = ((const float2*)(g_hw + (size_t)p6.x * DDIM))[lane];
        float2 v7 = ((const float2*)(g_hw + (size_t)p7.x * DDIM))[lane];
        ax += v0.x * __int_as_float(p0.y); ay += v0.y * __int_as_float(p0.y);
        ax += v1.x * __int_as_float(p1.y); ay += v1.y * __int_as_float(p1.y);
        ax += v2.x * __int_as_float(p2.y); ay += v2.y * __int_as_float(p2.y);
        ax += v3.x * __int_as_float(p3.y); ay += v3.y * __int_as_float(p3.y);
        ax += v4.x * __int_as_float(p4.y); ay += v4.y * __int_as_float(p4.y);
        ax += v5.x * __int_as_float(p5.y); ay += v5.y * __int_as_float(p5.y);
        ax += v6.x * __int_as_float(p6.y); ay += v6.y * __int_as_float(p6.y);
        ax += v7.x * __int_as_float(p7.y); ay += v7.y * __int_as_float(p7.y);
    }
    for (; i < end; ++i) {
        int2 p = g_epack[i];
        float2 v = ((const float2*)(g_hw + (size_t)p.x * DDIM))[lane];
        float nn = __int_as_float(p.y);
        ax += v.x * nn; ay += v.y * nn;
    }

    float2* o = (float2*)(out + (size_t)warp * DDIM);
    float2 base = o[lane];
    o[lane] = make_float2(fmaxf(base.x + ax, 0.0f), fmaxf(base.y + ay, 0.0f));
}

// ---------------------------------------------------------------------------
// Inputs (metadata order): h, norm, W, loop_weight, h_bias, src, dst, r
// 5 launches: hist, chunk_scan, scatter, gemm, agg.
// ---------------------------------------------------------------------------
extern "C" void kernel_launch(void* const* d_in, const int* in_sizes, int n_in,
                              void* d_out, int out_size)
{
    const float* h    = (const float*)d_in[0];
    const float* norm = (const float*)d_in[1];
    const float* W    = (const float*)d_in[2];
    const float* lw   = (const float*)d_in[3];
    const float* bias = (const float*)d_in[4];
    const int*   src  = (const int*)d_in[5];
    const int*   dst  = (const int*)d_in[6];
    const int*   rel  = (const int*)d_in[7];
    float* out = (float*)d_out;

    int n_nodes = in_sizes[0] / DDIM;
    int n_edges = in_sizes[5];

    int nb_edges = (n_edges + 255) / 256;
    int nchunks = (n_nodes + SCAN_CHUNK - 1) / SCAN_CHUNK;

    // CSR build (g_deg/g_blocksum pre-zeroed by previous replay's gemm,
    // or static zero-init on the very first call)
    hist_kernel<<<nb_edges, 256>>>(dst, n_edges, nchunks);
    chunk_scan_kernel<<<nchunks, SCAN_CHUNK>>>(n_nodes);
    scatter_build_kernel<<<nb_edges, 256>>>(src, dst, rel, norm, n_edges);

    // Fused tensor-core GEMM v2 (also re-zeros CSR counters for next replay)
    int ntiles = (n_nodes + 63) / 64;
    rgcn_gemm9_kernel<<<ntiles, 128>>>(h, W, lw, bias, out, n_nodes, nchunks);

    // Per-node aggregation: one warp per node, fused ReLU
    long long agg_threads = (long long)n_nodes * 32;
    agg_kernel<<<(int)((agg_threads + 255) / 256), 256>>>(out, n_nodes);
}